// round 7
// baseline (speedup 1.0000x reference)
#include <cuda_runtime.h>
#include <math.h>

#define S 65536
#define SMASK 65535
#define B 32
#define C 20
#define M 16
#define H 128

typedef unsigned long long u64;

static __device__ float g_h0[B*C*S];
static __device__ float g_h1[B*C*S];
static __device__ float g_cs[S];
static __device__ float g_sn[S];
static __device__ float g_partial[32*B*C*M*2];
static __device__ float g_X[B*C*M*2];
static __device__ float g_Y[B*C*M*2];
static __device__ float g_max[1];

__device__ __forceinline__ u64 pk2(float a, float b){
    u64 r; asm("mov.b64 %0,{%1,%2};" : "=l"(r) : "f"(a), "f"(b)); return r;
}
__device__ __forceinline__ void upk2(u64 v, float& a, float& b){
    asm("mov.b64 {%0,%1},%2;" : "=f"(a), "=f"(b) : "l"(v));
}
__device__ __forceinline__ u64 fma2(u64 a, u64 b, u64 c){
    u64 d; asm("fma.rn.f32x2 %0,%1,%2,%3;" : "=l"(d) : "l"(a), "l"(b), "l"(c)); return d;
}
__device__ __forceinline__ float geluf(float x){
    return 0.5f * x * (1.0f + erff(x * 0.7071067811865476f));
}

__global__ void k_max(const float* __restrict__ pd){
    __shared__ float red[1024];
    int tid = threadIdx.x;
    float m = -1e30f;
    for (int i = tid; i < S; i += 1024) m = fmaxf(m, pd[i]);
    red[tid] = m; __syncthreads();
    for (int o = 512; o >= 1; o >>= 1){
        if (tid < o) red[tid] = fmaxf(red[tid], red[tid+o]);
        __syncthreads();
    }
    if (tid == 0) g_max[0] = red[0];
}

__global__ void k_tables(){
    int i = blockIdx.x*1024 + threadIdx.x;
    if (i < S){
        float ang = (float)i * 9.587379924285257e-5f;  // 2*pi/65536
        float s, c; sincosf(ang, &s, &c);
        g_cs[i] = c; g_sn[i] = s;
    }
}

__global__ void __launch_bounds__(128) k_lift(const float* __restrict__ x,
                                              const float* __restrict__ pd,
                                              const float* __restrict__ fc0w,
                                              const float* __restrict__ fc0b){
    const int b = blockIdx.y;
    const int s0 = (blockIdx.x*128 + threadIdx.x)*4;
    const float inv = 1.0f / g_max[0];
    float4 xv = *(const float4*)&x[b*S + s0];
    float4 pv = *(const float4*)&pd[s0];
    float g0 = pv.x*inv, g1 = pv.y*inv, g2 = pv.z*inv, g3 = pv.w*inv;
    #pragma unroll
    for (int c = 0; c < C; c++){
        float wa = fc0w[c], wg = fc0w[C + c], bb = fc0b[c];
        float4 o;
        o.x = fmaf(xv.x, wa, fmaf(g0, wg, bb));
        o.y = fmaf(xv.y, wa, fmaf(g1, wg, bb));
        o.z = fmaf(xv.z, wa, fmaf(g2, wg, bb));
        o.w = fmaf(xv.w, wa, fmaf(g3, wg, bb));
        *(float4*)&g_h0[((b*C + c) << 16) + s0] = o;
    }
}

// forward truncated DFT over one 2048-sample chunk, one batch.
// 320 thr = 5 ch-groups(4ch) x 4 mode-groups(4m) x 16 k-slots.
__global__ void __launch_bounds__(320) k_dft(const float* __restrict__ h){
    __shared__ __align__(16) float h_sh[C][136];
    __shared__ __align__(16) float cs_sh[M][136];
    __shared__ __align__(16) float sn_sh[M][136];
    const int b = blockIdx.y, kch = blockIdx.x, tid = threadIdx.x;
    const int cg = tid >> 6, mg = (tid >> 4) & 3, ksub = tid & 15;
    u64 aRe[4][4], aIm[4][4];
    #pragma unroll
    for (int c = 0; c < 4; c++)
        #pragma unroll
        for (int m = 0; m < 4; m++){ aRe[c][m] = 0ull; aIm[c][m] = 0ull; }
    const int k0base = kch * 2048;
    for (int st = 0; st < 16; st++){
        const int k0 = k0base + st*128;
        for (int idx = tid; idx < C*128; idx += 320){
            int c = idx >> 7, k = idx & 127;
            h_sh[c][k] = h[((b*C + c) << 16) + k0 + k];
        }
        for (int idx = tid; idx < M*128; idx += 320){
            int m = idx >> 7, k = idx & 127;
            int t = (m*(k0 + k)) & SMASK;
            cs_sh[m][k] = g_cs[t]; sn_sh[m][k] = g_sn[t];
        }
        __syncthreads();
        #pragma unroll
        for (int i = 0; i < 4; i++){
            const int kk = (i*16 + ksub)*2;
            u64 hv[4], cv[4], sv[4];
            #pragma unroll
            for (int c = 0; c < 4; c++) hv[c] = *(const u64*)&h_sh[cg*4 + c][kk];
            #pragma unroll
            for (int m = 0; m < 4; m++){
                cv[m] = *(const u64*)&cs_sh[mg*4 + m][kk];
                sv[m] = *(const u64*)&sn_sh[mg*4 + m][kk];
            }
            #pragma unroll
            for (int c = 0; c < 4; c++)
                #pragma unroll
                for (int m = 0; m < 4; m++){
                    aRe[c][m] = fma2(hv[c], cv[m], aRe[c][m]);
                    aIm[c][m] = fma2(hv[c], sv[m], aIm[c][m]);
                }
        }
        __syncthreads();
    }
    #pragma unroll
    for (int c = 0; c < 4; c++)
        #pragma unroll
        for (int m = 0; m < 4; m++){
            float r0, r1, i0, i1;
            upk2(aRe[c][m], r0, r1); upk2(aIm[c][m], i0, i1);
            float r = r0 + r1, im = i0 + i1;
            #pragma unroll
            for (int off = 8; off >= 1; off >>= 1){
                r  += __shfl_down_sync(0xffffffffu, r,  off, 16);
                im += __shfl_down_sync(0xffffffffu, im, off, 16);
            }
            if (ksub == 0){
                int base = (((kch*B + b)*C + cg*4 + c)*M + (mg*4 + m))*2;
                g_partial[base]   = r;
                g_partial[base+1] = -im;   // X[m] = sum h e^{-i theta}
            }
        }
}

__global__ void k_reduceX(){
    int i = blockIdx.x*256 + threadIdx.x;
    if (i < B*C*M*2){
        float s = 0.f;
        #pragma unroll
        for (int k = 0; k < 32; k++) s += g_partial[k*(B*C*M*2) + i];
        g_X[i] = s;
    }
}

// complex channel mixing + irfft scaling (DC: Re only, x1/S; m>=1: x2/S)
__global__ void k_mix(const float* __restrict__ wre, const float* __restrict__ wim){
    int idx = blockIdx.x*256 + threadIdx.x;
    if (idx >= B*C*M) return;
    int b = idx / (C*M), r = idx % (C*M), co = r / M, m = r % M;
    float yr = 0.f, yi = 0.f;
    for (int ci = 0; ci < C; ci++){
        float xr = g_X[((b*C + ci)*M + m)*2];
        float xi = g_X[((b*C + ci)*M + m)*2 + 1];
        float wr = wre[(ci*C + co)*M + m];
        float wi = wim[(ci*C + co)*M + m];
        yr += xr*wr - xi*wi;
        yi += xr*wi + xi*wr;
    }
    const float invS = 1.0f / (float)S;
    if (m == 0){ yr *= invS; yi = 0.f; }
    else       { yr *= 2.0f*invS; yi *= 2.0f*invS; }
    g_Y[((b*C + co)*M + m)*2]     = yr;
    g_Y[((b*C + co)*M + m)*2 + 1] = yi;
}

// fused inverse-DFT + 1x1 conv + bias + gelu
__global__ void __launch_bounds__(128) k_layer(const float* __restrict__ hin,
                                               float* __restrict__ hout,
                                               const float* __restrict__ ww,
                                               const float* __restrict__ wb){
    __shared__ __align__(8) u64 Yr2[C][M];
    __shared__ __align__(8) u64 Yi2n[C][M];
    __shared__ __align__(8) u64 W2[C][C];
    __shared__ float Y0b[C];
    const int b = blockIdx.y, tid = threadIdx.x;
    for (int idx = tid; idx < C*M; idx += 128){
        int co = idx >> 4, m = idx & 15;
        float yr = g_Y[((b*C + co)*M + m)*2];
        float yi = g_Y[((b*C + co)*M + m)*2 + 1];
        Yr2[co][m]  = pk2(yr, yr);
        Yi2n[co][m] = pk2(-yi, -yi);
        if (m == 0) Y0b[co] = yr + wb[co];
    }
    for (int idx = tid; idx < C*C; idx += 128){
        int o = idx / C, c = idx % C;
        float w = ww[o*C + c];
        W2[o][c] = pk2(w, w);
    }
    __syncthreads();
    const int s0 = (blockIdx.x*128 + tid)*4;
    u64 a0[C], a1[C];
    #pragma unroll
    for (int co = 0; co < C; co++){ float v = Y0b[co]; a0[co] = pk2(v, v); a1[co] = a0[co]; }
    for (int ci = 0; ci < C; ci++){
        float4 hv = *(const float4*)&hin[((b*C + ci) << 16) + s0];
        u64 hA = pk2(hv.x, hv.y), hB = pk2(hv.z, hv.w);
        #pragma unroll
        for (int co = 0; co < C; co++){
            u64 w = W2[co][ci];
            a0[co] = fma2(hA, w, a0[co]);
            a1[co] = fma2(hB, w, a1[co]);
        }
    }
    #pragma unroll
    for (int m = 1; m < M; m++){
        int i0 = (m*s0) & SMASK, i1 = (i0+m) & SMASK, i2 = (i1+m) & SMASK, i3 = (i2+m) & SMASK;
        u64 cA = pk2(g_cs[i0], g_cs[i1]), cB = pk2(g_cs[i2], g_cs[i3]);
        u64 sA = pk2(g_sn[i0], g_sn[i1]), sB = pk2(g_sn[i2], g_sn[i3]);
        #pragma unroll
        for (int co = 0; co < C; co++){
            u64 yr = Yr2[co][m], yin = Yi2n[co][m];
            a0[co] = fma2(cA, yr, a0[co]);
            a1[co] = fma2(cB, yr, a1[co]);
            a0[co] = fma2(sA, yin, a0[co]);
            a1[co] = fma2(sB, yin, a1[co]);
        }
    }
    #pragma unroll
    for (int co = 0; co < C; co++){
        float f0, f1, f2, f3;
        upk2(a0[co], f0, f1); upk2(a1[co], f2, f3);
        float4 o;
        o.x = geluf(f0); o.y = geluf(f1); o.z = geluf(f2); o.w = geluf(f3);
        *(float4*)&hout[((b*C + co) << 16) + s0] = o;
    }
}

// layer 3 (no gelu) fused with fc1+gelu+fc2 -> final output
__global__ void __launch_bounds__(128) k_final(const float* __restrict__ hin,
                                               const float* __restrict__ ww,
                                               const float* __restrict__ wb,
                                               const float* __restrict__ fc1w,
                                               const float* __restrict__ fc1b,
                                               const float* __restrict__ fc2w,
                                               const float* __restrict__ fc2b,
                                               float* __restrict__ out){
    __shared__ __align__(8) u64 Yr2[C][M];
    __shared__ __align__(8) u64 Yi2n[C][M];
    __shared__ __align__(8) u64 W2[C][C];
    __shared__ float Y0b[C];
    __shared__ __align__(8) u64 F1[C][H];
    __shared__ float f1b[H];
    __shared__ float f2w[H];
    const int b = blockIdx.y, tid = threadIdx.x;
    for (int idx = tid; idx < C*M; idx += 128){
        int co = idx >> 4, m = idx & 15;
        float yr = g_Y[((b*C + co)*M + m)*2];
        float yi = g_Y[((b*C + co)*M + m)*2 + 1];
        Yr2[co][m]  = pk2(yr, yr);
        Yi2n[co][m] = pk2(-yi, -yi);
        if (m == 0) Y0b[co] = yr + wb[co];
    }
    for (int idx = tid; idx < C*C; idx += 128){
        int o = idx / C, c = idx % C;
        float w = ww[o*C + c];
        W2[o][c] = pk2(w, w);
    }
    for (int idx = tid; idx < C*H; idx += 128){
        int c = idx >> 7, j = idx & 127;
        float w = fc1w[c*H + j];
        F1[c][j] = pk2(w, w);
    }
    for (int idx = tid; idx < H; idx += 128){ f1b[idx] = fc1b[idx]; f2w[idx] = fc2w[idx]; }
    __syncthreads();
    const int s0 = (blockIdx.x*128 + tid)*4;
    u64 a0[C], a1[C];
    #pragma unroll
    for (int co = 0; co < C; co++){ float v = Y0b[co]; a0[co] = pk2(v, v); a1[co] = a0[co]; }
    for (int ci = 0; ci < C; ci++){
        float4 hv = *(const float4*)&hin[((b*C + ci) << 16) + s0];
        u64 hA = pk2(hv.x, hv.y), hB = pk2(hv.z, hv.w);
        #pragma unroll
        for (int co = 0; co < C; co++){
            u64 w = W2[co][ci];
            a0[co] = fma2(hA, w, a0[co]);
            a1[co] = fma2(hB, w, a1[co]);
        }
    }
    #pragma unroll
    for (int m = 1; m < M; m++){
        int i0 = (m*s0) & SMASK, i1 = (i0+m) & SMASK, i2 = (i1+m) & SMASK, i3 = (i2+m) & SMASK;
        u64 cA = pk2(g_cs[i0], g_cs[i1]), cB = pk2(g_cs[i2], g_cs[i3]);
        u64 sA = pk2(g_sn[i0], g_sn[i1]), sB = pk2(g_sn[i2], g_sn[i3]);
        #pragma unroll
        for (int co = 0; co < C; co++){
            u64 yr = Yr2[co][m], yin = Yi2n[co][m];
            a0[co] = fma2(cA, yr, a0[co]);
            a1[co] = fma2(cB, yr, a1[co]);
            a0[co] = fma2(sA, yin, a0[co]);
            a1[co] = fma2(sB, yin, a1[co]);
        }
    }
    float o0, o1, o2, o3;
    o0 = o1 = o2 = o3 = fc2b[0];
    for (int j = 0; j < H; j++){
        float bj = f1b[j];
        u64 t0 = pk2(bj, bj), t1 = t0;
        #pragma unroll
        for (int c = 0; c < C; c++){
            u64 f = F1[c][j];
            t0 = fma2(a0[c], f, t0);
            t1 = fma2(a1[c], f, t1);
        }
        float u0, u1, u2, u3;
        upk2(t0, u0, u1); upk2(t1, u2, u3);
        float w = f2w[j];
        o0 = fmaf(geluf(u0), w, o0);
        o1 = fmaf(geluf(u1), w, o1);
        o2 = fmaf(geluf(u2), w, o2);
        o3 = fmaf(geluf(u3), w, o3);
    }
    float4 res; res.x = o0; res.y = o1; res.z = o2; res.w = o3;
    *(float4*)&out[b*S + s0] = res;
}

extern "C" void kernel_launch(void* const* d_in, const int* in_sizes, int n_in,
                              void* d_out, int out_size){
    float *h0, *h1;
    cudaGetSymbolAddress((void**)&h0, g_h0);
    cudaGetSymbolAddress((void**)&h1, g_h1);

    const float* x    = (const float*)d_in[0];
    const float* pd   = (const float*)d_in[1];
    const float* fc0w = (const float*)d_in[2];
    const float* fc0b = (const float*)d_in[3];

    // Two possible input orderings:
    //  (a) reference() signature order: sw0_re at index 4 (6400 elements)
    //  (b) setup_inputs() dict order:   fc1_w at index 4 (2560 elements)
    const float *swre[4], *swim[4], *wlw[4], *wlb[4];
    const float *fc1w, *fc1b, *fc2w, *fc2b;
    if (in_sizes[4] == C*C*M){           // signature order
        for (int l = 0; l < 4; l++){
            swre[l] = (const float*)d_in[4 + 4*l];
            swim[l] = (const float*)d_in[5 + 4*l];
            wlw[l]  = (const float*)d_in[6 + 4*l];
            wlb[l]  = (const float*)d_in[7 + 4*l];
        }
        fc1w = (const float*)d_in[20];
        fc1b = (const float*)d_in[21];
        fc2w = (const float*)d_in[22];
        fc2b = (const float*)d_in[23];
    } else {                             // dict-insertion order
        fc1w = (const float*)d_in[4];
        fc1b = (const float*)d_in[5];
        fc2w = (const float*)d_in[6];
        fc2b = (const float*)d_in[7];
        for (int l = 0; l < 4; l++){
            swre[l] = (const float*)d_in[8  + 4*l];
            swim[l] = (const float*)d_in[9  + 4*l];
            wlw[l]  = (const float*)d_in[10 + 4*l];
            wlb[l]  = (const float*)d_in[11 + 4*l];
        }
    }
    float* out = (float*)d_out;

    k_max<<<1, 1024>>>(pd);
    k_tables<<<64, 1024>>>();
    k_lift<<<dim3(S/512, B), 128>>>(x, pd, fc0w, fc0b);

    float* hin = h0;
    float* hout = h1;
    for (int l = 0; l < 4; l++){
        k_dft<<<dim3(32, B), 320>>>(hin);
        k_reduceX<<<(B*C*M*2 + 255)/256, 256>>>();
        k_mix<<<(B*C*M + 255)/256, 256>>>(swre[l], swim[l]);
        if (l < 3){
            k_layer<<<dim3(S/512, B), 128>>>(hin, hout, wlw[l], wlb[l]);
            float* t = hin; hin = hout; hout = t;
        } else {
            k_final<<<dim3(S/512, B), 128>>>(hin, wlw[3], wlb[3],
                                             fc1w, fc1b, fc2w, fc2b, out);
        }
    }
}

// round 9
// speedup vs baseline: 1.0400x; 1.0400x over previous
#include <cuda_runtime.h>
#include <math.h>

#define S 65536
#define SMASK 65535
#define B 32
#define C 20
#define M 16
#define H 128
#define DCHUNK 8192
#define NCHUNK (S/DCHUNK)   // 8

typedef unsigned long long u64;

static __device__ float g_h0[B*C*S];
static __device__ float g_h1[B*C*S];
static __device__ float g_cs[S];
static __device__ float g_sn[S];
static __device__ float g_Tc[M*S];            // cos(2pi m s/S), m-major
static __device__ float g_Ts[M*S];            // -sin(2pi m s/S)
static __device__ float g_partial[NCHUNK*B*C*M*2];
static __device__ float g_X[B*C*M*2];
static __device__ float g_Y[B*C*M*2];
static __device__ float g_max[1];

__device__ __forceinline__ u64 pk2(float a, float b){
    u64 r; asm("mov.b64 %0,{%1,%2};" : "=l"(r) : "f"(a), "f"(b)); return r;
}
__device__ __forceinline__ void upk2(u64 v, float& a, float& b){
    asm("mov.b64 {%0,%1},%2;" : "=f"(a), "=f"(b) : "l"(v));
}
__device__ __forceinline__ u64 fma2(u64 a, u64 b, u64 c){
    u64 d; asm("fma.rn.f32x2 %0,%1,%2,%3;" : "=l"(d) : "l"(a), "l"(b), "l"(c)); return d;
}
__device__ __forceinline__ float geluf(float x){
    return 0.5f * x * (1.0f + erff(x * 0.7071067811865476f));
}

__global__ void k_max(const float* __restrict__ pd){
    __shared__ float red[1024];
    int tid = threadIdx.x;
    float m = -1e30f;
    for (int i = tid; i < S; i += 1024) m = fmaxf(m, pd[i]);
    red[tid] = m; __syncthreads();
    for (int o = 512; o >= 1; o >>= 1){
        if (tid < o) red[tid] = fmaxf(red[tid], red[tid+o]);
        __syncthreads();
    }
    if (tid == 0) g_max[0] = red[0];
}

__global__ void k_tables(){
    int i = blockIdx.x*1024 + threadIdx.x;
    if (i < S){
        float ang = (float)i * 9.587379924285257e-5f;  // 2*pi/65536
        float s, c; sincosf(ang, &s, &c);
        g_cs[i] = c; g_sn[i] = s;
    }
}

__global__ void k_ttab(){
    int i = blockIdx.x*1024 + threadIdx.x;   // i = m*S + s, M*S = 1048576
    int m = i >> 16, s = i & SMASK;
    int t = (m*s) & SMASK;
    g_Tc[i] = g_cs[t];
    g_Ts[i] = -g_sn[t];
}

__global__ void __launch_bounds__(128) k_lift(const float* __restrict__ x,
                                              const float* __restrict__ pd,
                                              const float* __restrict__ fc0w,
                                              const float* __restrict__ fc0b){
    const int b = blockIdx.y;
    const int s0 = (blockIdx.x*128 + threadIdx.x)*4;
    const float inv = 1.0f / g_max[0];
    float4 xv = *(const float4*)&x[b*S + s0];
    float4 pv = *(const float4*)&pd[s0];
    float g0 = pv.x*inv, g1 = pv.y*inv, g2 = pv.z*inv, g3 = pv.w*inv;
    #pragma unroll
    for (int c = 0; c < C; c++){
        float wa = fc0w[c], wg = fc0w[C + c], bb = fc0b[c];
        float4 o;
        o.x = fmaf(xv.x, wa, fmaf(g0, wg, bb));
        o.y = fmaf(xv.y, wa, fmaf(g1, wg, bb));
        o.z = fmaf(xv.z, wa, fmaf(g2, wg, bb));
        o.w = fmaf(xv.w, wa, fmaf(g3, wg, bb));
        *(float4*)&g_h0[((b*C + c) << 16) + s0] = o;
    }
}

// streaming forward truncated DFT, barrier-free.
// block = 640 thr = 20 warps; warp owns a 4ch x 4mode tile; lanes stride s.
// grid = (NCHUNK, B); each block covers an 8192-sample chunk of one batch.
__global__ void __launch_bounds__(640, 1) k_dft2(const float* __restrict__ h){
    const int b = blockIdx.y, ch = blockIdx.x;
    const int w = threadIdx.x >> 5, lane = threadIdx.x & 31;
    const int cg = w >> 2, mg = w & 3;        // cg 0..4, mg 0..3
    const int c0 = cg*4, m0 = mg*4;
    const int sbase = ch*DCHUNK + lane*4;
    u64 accR[4][4], accI[4][4];
    #pragma unroll
    for (int c = 0; c < 4; c++)
        #pragma unroll
        for (int m = 0; m < 4; m++){ accR[c][m] = 0ull; accI[c][m] = 0ull; }
    const float* hb = h + ((b*C + c0) << 16);
    for (int it = 0; it < DCHUNK/128; it++){
        const int s = sbase + it*128;
        // hoist the 4 channel vectors (16 regs live)
        float4 hv0 = *(const float4*)&hb[(0<<16) + s];
        float4 hv1 = *(const float4*)&hb[(1<<16) + s];
        float4 hv2 = *(const float4*)&hb[(2<<16) + s];
        float4 hv3 = *(const float4*)&hb[(3<<16) + s];
        u64 h0lo = pk2(hv0.x, hv0.y), h0hi = pk2(hv0.z, hv0.w);
        u64 h1lo = pk2(hv1.x, hv1.y), h1hi = pk2(hv1.z, hv1.w);
        u64 h2lo = pk2(hv2.x, hv2.y), h2hi = pk2(hv2.z, hv2.w);
        u64 h3lo = pk2(hv3.x, hv3.y), h3hi = pk2(hv3.z, hv3.w);
        #pragma unroll
        for (int m = 0; m < 4; m++){
            float4 tc = *(const float4*)&g_Tc[((m0+m)<<16) + s];
            float4 ts = *(const float4*)&g_Ts[((m0+m)<<16) + s];
            u64 clo = pk2(tc.x, tc.y), chi = pk2(tc.z, tc.w);
            u64 slo = pk2(ts.x, ts.y), shi = pk2(ts.z, ts.w);
            accR[0][m] = fma2(h0lo, clo, accR[0][m]);
            accR[0][m] = fma2(h0hi, chi, accR[0][m]);
            accI[0][m] = fma2(h0lo, slo, accI[0][m]);
            accI[0][m] = fma2(h0hi, shi, accI[0][m]);
            accR[1][m] = fma2(h1lo, clo, accR[1][m]);
            accR[1][m] = fma2(h1hi, chi, accR[1][m]);
            accI[1][m] = fma2(h1lo, slo, accI[1][m]);
            accI[1][m] = fma2(h1hi, shi, accI[1][m]);
            accR[2][m] = fma2(h2lo, clo, accR[2][m]);
            accR[2][m] = fma2(h2hi, chi, accR[2][m]);
            accI[2][m] = fma2(h2lo, slo, accI[2][m]);
            accI[2][m] = fma2(h2hi, shi, accI[2][m]);
            accR[3][m] = fma2(h3lo, clo, accR[3][m]);
            accR[3][m] = fma2(h3hi, chi, accR[3][m]);
            accI[3][m] = fma2(h3lo, slo, accI[3][m]);
            accI[3][m] = fma2(h3hi, shi, accI[3][m]);
        }
    }
    #pragma unroll
    for (int c = 0; c < 4; c++)
        #pragma unroll
        for (int m = 0; m < 4; m++){
            float r0, r1, i0, i1;
            upk2(accR[c][m], r0, r1); upk2(accI[c][m], i0, i1);
            float r = r0 + r1, im = i0 + i1;
            #pragma unroll
            for (int off = 16; off >= 1; off >>= 1){
                r  += __shfl_down_sync(0xffffffffu, r,  off);
                im += __shfl_down_sync(0xffffffffu, im, off);
            }
            if (lane == 0){
                int base = (((ch*B + b)*C + c0 + c)*M + (m0 + m))*2;
                g_partial[base]   = r;
                g_partial[base+1] = im;   // Ts already holds -sin
            }
        }
}

__global__ void k_reduceX(){
    int i = blockIdx.x*256 + threadIdx.x;
    if (i < B*C*M*2){
        float s = 0.f;
        #pragma unroll
        for (int k = 0; k < NCHUNK; k++) s += g_partial[k*(B*C*M*2) + i];
        g_X[i] = s;
    }
}

// complex channel mixing + irfft scaling (DC: Re only, x1/S; m>=1: x2/S)
__global__ void k_mix(const float* __restrict__ wre, const float* __restrict__ wim){
    int idx = blockIdx.x*256 + threadIdx.x;
    if (idx >= B*C*M) return;
    int b = idx / (C*M), r = idx % (C*M), co = r / M, m = r % M;
    float yr = 0.f, yi = 0.f;
    for (int ci = 0; ci < C; ci++){
        float xr = g_X[((b*C + ci)*M + m)*2];
        float xi = g_X[((b*C + ci)*M + m)*2 + 1];
        float wr = wre[(ci*C + co)*M + m];
        float wi = wim[(ci*C + co)*M + m];
        yr += xr*wr - xi*wi;
        yi += xr*wi + xi*wr;
    }
    const float invS = 1.0f / (float)S;
    if (m == 0){ yr *= invS; yi = 0.f; }
    else       { yr *= 2.0f*invS; yi *= 2.0f*invS; }
    g_Y[((b*C + co)*M + m)*2]     = yr;
    g_Y[((b*C + co)*M + m)*2 + 1] = yi;
}

// fused inverse-DFT + 1x1 conv + bias + gelu
__global__ void __launch_bounds__(128) k_layer(const float* __restrict__ hin,
                                               float* __restrict__ hout,
                                               const float* __restrict__ ww,
                                               const float* __restrict__ wb){
    __shared__ __align__(8) u64 Yr2[C][M];
    __shared__ __align__(8) u64 Yi2n[C][M];
    __shared__ __align__(8) u64 W2[C][C];
    __shared__ float Y0b[C];
    const int b = blockIdx.y, tid = threadIdx.x;
    for (int idx = tid; idx < C*M; idx += 128){
        int co = idx >> 4, m = idx & 15;
        float yr = g_Y[((b*C + co)*M + m)*2];
        float yi = g_Y[((b*C + co)*M + m)*2 + 1];
        Yr2[co][m]  = pk2(yr, yr);
        Yi2n[co][m] = pk2(-yi, -yi);
        if (m == 0) Y0b[co] = yr + wb[co];
    }
    for (int idx = tid; idx < C*C; idx += 128){
        int o = idx / C, c = idx % C;
        float w = ww[o*C + c];
        W2[o][c] = pk2(w, w);
    }
    __syncthreads();
    const int s0 = (blockIdx.x*128 + tid)*4;
    u64 a0[C], a1[C];
    #pragma unroll
    for (int co = 0; co < C; co++){ float v = Y0b[co]; a0[co] = pk2(v, v); a1[co] = a0[co]; }
    for (int ci = 0; ci < C; ci++){
        float4 hv = *(const float4*)&hin[((b*C + ci) << 16) + s0];
        u64 hA = pk2(hv.x, hv.y), hB = pk2(hv.z, hv.w);
        #pragma unroll
        for (int co = 0; co < C; co++){
            u64 w = W2[co][ci];
            a0[co] = fma2(hA, w, a0[co]);
            a1[co] = fma2(hB, w, a1[co]);
        }
    }
    #pragma unroll
    for (int m = 1; m < M; m++){
        int i0 = (m*s0) & SMASK, i1 = (i0+m) & SMASK, i2 = (i1+m) & SMASK, i3 = (i2+m) & SMASK;
        u64 cA = pk2(g_cs[i0], g_cs[i1]), cB = pk2(g_cs[i2], g_cs[i3]);
        u64 sA = pk2(g_sn[i0], g_sn[i1]), sB = pk2(g_sn[i2], g_sn[i3]);
        #pragma unroll
        for (int co = 0; co < C; co++){
            u64 yr = Yr2[co][m], yin = Yi2n[co][m];
            a0[co] = fma2(cA, yr, a0[co]);
            a1[co] = fma2(cB, yr, a1[co]);
            a0[co] = fma2(sA, yin, a0[co]);
            a1[co] = fma2(sB, yin, a1[co]);
        }
    }
    #pragma unroll
    for (int co = 0; co < C; co++){
        float f0, f1, f2, f3;
        upk2(a0[co], f0, f1); upk2(a1[co], f2, f3);
        float4 o;
        o.x = geluf(f0); o.y = geluf(f1); o.z = geluf(f2); o.w = geluf(f3);
        *(float4*)&hout[((b*C + co) << 16) + s0] = o;
    }
}

// layer 3 (no gelu) fused with fc1+gelu+fc2 -> final output
__global__ void __launch_bounds__(128) k_final(const float* __restrict__ hin,
                                               const float* __restrict__ ww,
                                               const float* __restrict__ wb,
                                               const float* __restrict__ fc1w,
                                               const float* __restrict__ fc1b,
                                               const float* __restrict__ fc2w,
                                               const float* __restrict__ fc2b,
                                               float* __restrict__ out){
    __shared__ __align__(8) u64 Yr2[C][M];
    __shared__ __align__(8) u64 Yi2n[C][M];
    __shared__ __align__(8) u64 W2[C][C];
    __shared__ float Y0b[C];
    __shared__ __align__(8) u64 F1[C][H];
    __shared__ float f1b[H];
    __shared__ float f2w[H];
    const int b = blockIdx.y, tid = threadIdx.x;
    for (int idx = tid; idx < C*M; idx += 128){
        int co = idx >> 4, m = idx & 15;
        float yr = g_Y[((b*C + co)*M + m)*2];
        float yi = g_Y[((b*C + co)*M + m)*2 + 1];
        Yr2[co][m]  = pk2(yr, yr);
        Yi2n[co][m] = pk2(-yi, -yi);
        if (m == 0) Y0b[co] = yr + wb[co];
    }
    for (int idx = tid; idx < C*C; idx += 128){
        int o = idx / C, c = idx % C;
        float w = ww[o*C + c];
        W2[o][c] = pk2(w, w);
    }
    for (int idx = tid; idx < C*H; idx += 128){
        int c = idx >> 7, j = idx & 127;
        float w = fc1w[c*H + j];
        F1[c][j] = pk2(w, w);
    }
    for (int idx = tid; idx < H; idx += 128){ f1b[idx] = fc1b[idx]; f2w[idx] = fc2w[idx]; }
    __syncthreads();
    const int s0 = (blockIdx.x*128 + tid)*4;
    u64 a0[C], a1[C];
    #pragma unroll
    for (int co = 0; co < C; co++){ float v = Y0b[co]; a0[co] = pk2(v, v); a1[co] = a0[co]; }
    for (int ci = 0; ci < C; ci++){
        float4 hv = *(const float4*)&hin[((b*C + ci) << 16) + s0];
        u64 hA = pk2(hv.x, hv.y), hB = pk2(hv.z, hv.w);
        #pragma unroll
        for (int co = 0; co < C; co++){
            u64 w = W2[co][ci];
            a0[co] = fma2(hA, w, a0[co]);
            a1[co] = fma2(hB, w, a1[co]);
        }
    }
    #pragma unroll
    for (int m = 1; m < M; m++){
        int i0 = (m*s0) & SMASK, i1 = (i0+m) & SMASK, i2 = (i1+m) & SMASK, i3 = (i2+m) & SMASK;
        u64 cA = pk2(g_cs[i0], g_cs[i1]), cB = pk2(g_cs[i2], g_cs[i3]);
        u64 sA = pk2(g_sn[i0], g_sn[i1]), sB = pk2(g_sn[i2], g_sn[i3]);
        #pragma unroll
        for (int co = 0; co < C; co++){
            u64 yr = Yr2[co][m], yin = Yi2n[co][m];
            a0[co] = fma2(cA, yr, a0[co]);
            a1[co] = fma2(cB, yr, a1[co]);
            a0[co] = fma2(sA, yin, a0[co]);
            a1[co] = fma2(sB, yin, a1[co]);
        }
    }
    float o0, o1, o2, o3;
    o0 = o1 = o2 = o3 = fc2b[0];
    for (int j = 0; j < H; j++){
        float bj = f1b[j];
        u64 t0 = pk2(bj, bj), t1 = t0;
        #pragma unroll
        for (int c = 0; c < C; c++){
            u64 f = F1[c][j];
            t0 = fma2(a0[c], f, t0);
            t1 = fma2(a1[c], f, t1);
        }
        float u0, u1, u2, u3;
        upk2(t0, u0, u1); upk2(t1, u2, u3);
        float w = f2w[j];
        o0 = fmaf(geluf(u0), w, o0);
        o1 = fmaf(geluf(u1), w, o1);
        o2 = fmaf(geluf(u2), w, o2);
        o3 = fmaf(geluf(u3), w, o3);
    }
    float4 res; res.x = o0; res.y = o1; res.z = o2; res.w = o3;
    *(float4*)&out[b*S + s0] = res;
}

extern "C" void kernel_launch(void* const* d_in, const int* in_sizes, int n_in,
                              void* d_out, int out_size){
    float *h0, *h1;
    cudaGetSymbolAddress((void**)&h0, g_h0);
    cudaGetSymbolAddress((void**)&h1, g_h1);

    const float* x    = (const float*)d_in[0];
    const float* pd   = (const float*)d_in[1];
    const float* fc0w = (const float*)d_in[2];
    const float* fc0b = (const float*)d_in[3];

    const float *swre[4], *swim[4], *wlw[4], *wlb[4];
    const float *fc1w, *fc1b, *fc2w, *fc2b;
    if (in_sizes[4] == C*C*M){           // signature order
        for (int l = 0; l < 4; l++){
            swre[l] = (const float*)d_in[4 + 4*l];
            swim[l] = (const float*)d_in[5 + 4*l];
            wlw[l]  = (const float*)d_in[6 + 4*l];
            wlb[l]  = (const float*)d_in[7 + 4*l];
        }
        fc1w = (const float*)d_in[20];
        fc1b = (const float*)d_in[21];
        fc2w = (const float*)d_in[22];
        fc2b = (const float*)d_in[23];
    } else {                             // dict-insertion order
        fc1w = (const float*)d_in[4];
        fc1b = (const float*)d_in[5];
        fc2w = (const float*)d_in[6];
        fc2b = (const float*)d_in[7];
        for (int l = 0; l < 4; l++){
            swre[l] = (const float*)d_in[8  + 4*l];
            swim[l] = (const float*)d_in[9  + 4*l];
            wlw[l]  = (const float*)d_in[10 + 4*l];
            wlb[l]  = (const float*)d_in[11 + 4*l];
        }
    }
    float* out = (float*)d_out;

    k_max<<<1, 1024>>>(pd);
    k_tables<<<64, 1024>>>();
    k_ttab<<<(M*S)/1024, 1024>>>();
    k_lift<<<dim3(S/512, B), 128>>>(x, pd, fc0w, fc0b);

    float* hin = h0;
    float* hout = h1;
    for (int l = 0; l < 4; l++){
        k_dft2<<<dim3(NCHUNK, B), 640>>>(hin);
        k_reduceX<<<(B*C*M*2 + 255)/256, 256>>>();
        k_mix<<<(B*C*M + 255)/256, 256>>>(swre[l], swim[l]);
        if (l < 3){
            k_layer<<<dim3(S/512, B), 128>>>(hin, hout, wlw[l], wlb[l]);
            float* t = hin; hin = hout; hout = t;
        } else {
            k_final<<<dim3(S/512, B), 128>>>(hin, wlw[3], wlb[3],
                                             fc1w, fc1b, fc2w, fc2b, out);
        }
    }
}

// round 10
// speedup vs baseline: 1.4237x; 1.3689x over previous
#include <cuda_runtime.h>
#include <math.h>

#define S 65536
#define SMASK 65535
#define B 32
#define C 20
#define M 16
#define H 128
#define PTS 1024                 // points per fused block
#define NCHUNK (S/PTS)           // 64

typedef unsigned long long u64;

static __device__ float g_h0[B*C*S];
static __device__ float g_h1[B*C*S];
static __device__ float g_cs[S];
static __device__ float g_sn[S];
static __device__ float g_Tc[M*S];            // cos(2pi m s/S), m-major
static __device__ float g_Ts[M*S];            // -sin(2pi m s/S), m-major
static __device__ float g_partial[NCHUNK*B*C*M*2];
static __device__ float g_X[B*C*M*2];
static __device__ float g_Y[B*C*M*2];
static __device__ float g_max[1];

__device__ __forceinline__ u64 pk2(float a, float b){
    u64 r; asm("mov.b64 %0,{%1,%2};" : "=l"(r) : "f"(a), "f"(b)); return r;
}
__device__ __forceinline__ void upk2(u64 v, float& a, float& b){
    asm("mov.b64 {%0,%1},%2;" : "=f"(a), "=f"(b) : "l"(v));
}
__device__ __forceinline__ u64 fma2(u64 a, u64 b, u64 c){
    u64 d; asm("fma.rn.f32x2 %0,%1,%2,%3;" : "=l"(d) : "l"(a), "l"(b), "l"(c)); return d;
}
// gelu via Abramowitz-Stegun 7.1.26 erf approximation (|abs err| <= 1.5e-7)
__device__ __forceinline__ float geluf(float x){
    float z  = 0.7071067811865476f * x;
    float az = fabsf(z);
    float t  = __fdividef(1.0f, fmaf(0.3275911f, az, 1.0f));
    float p  = fmaf(1.061405429f, t, -1.453152027f);
    p = fmaf(p, t, 1.421413741f);
    p = fmaf(p, t, -0.284496736f);
    p = fmaf(p, t, 0.254829592f);
    p = p * t;
    float e  = __expf(-az*az);
    float er = fmaf(-p, e, 1.0f);          // erf(|z|)
    er = copysignf(er, z);
    return 0.5f * x * (1.0f + er);
}

__global__ void k_max(const float* __restrict__ pd){
    __shared__ float red[1024];
    int tid = threadIdx.x;
    float m = -1e30f;
    for (int i = tid; i < S; i += 1024) m = fmaxf(m, pd[i]);
    red[tid] = m; __syncthreads();
    for (int o = 512; o >= 1; o >>= 1){
        if (tid < o) red[tid] = fmaxf(red[tid], red[tid+o]);
        __syncthreads();
    }
    if (tid == 0) g_max[0] = red[0];
}

__global__ void k_tables(){
    int i = blockIdx.x*1024 + threadIdx.x;
    if (i < S){
        float ang = (float)i * 9.587379924285257e-5f;  // 2*pi/65536
        float s, c; sincosf(ang, &s, &c);
        g_cs[i] = c; g_sn[i] = s;
    }
}

__global__ void k_ttab(){
    int i = blockIdx.x*1024 + threadIdx.x;   // i = m*S + s
    int m = i >> 16, s = i & SMASK;
    int t = (m*s) & SMASK;
    g_Tc[i] = g_cs[t];
    g_Ts[i] = -g_sn[t];
}

// ---- shared phase-2: block-local forward DFT of h over its PTS points ----
// 16 warps: warp tile = 5 channels x 4 modes. Lane owns 2-pt u64 slots.
// Reads h from GLOBAL (just written by this block; visible after syncthreads).
__device__ __forceinline__ void dft_phase(const float* __restrict__ hsrc,
                                          int b, int chunk){
    const int w = threadIdx.x >> 5, lane = threadIdx.x & 31;
    const int c0 = (w >> 2) * 5;      // 0,5,10,15
    const int m0 = (w & 3) * 4;       // 0,4,8,12
    const int p0 = chunk * PTS;
    u64 accR[5][4], accI[5][4];
    #pragma unroll
    for (int c = 0; c < 5; c++)
        #pragma unroll
        for (int m = 0; m < 4; m++){ accR[c][m] = 0ull; accI[c][m] = 0ull; }
    const float* hb = hsrc + ((b*C + c0) << 16);
    #pragma unroll 4
    for (int it = 0; it < PTS/64; it++){
        const int s = p0 + it*64 + lane*2;
        u64 hv[5];
        #pragma unroll
        for (int c = 0; c < 5; c++){
            float2 t = *(const float2*)&hb[(c<<16) + s];
            hv[c] = pk2(t.x, t.y);
        }
        #pragma unroll
        for (int m = 0; m < 4; m++){
            float2 tc = *(const float2*)&g_Tc[((m0+m)<<16) + s];
            float2 ts = *(const float2*)&g_Ts[((m0+m)<<16) + s];
            u64 cp = pk2(tc.x, tc.y);
            u64 sp = pk2(ts.x, ts.y);
            #pragma unroll
            for (int c = 0; c < 5; c++){
                accR[c][m] = fma2(hv[c], cp, accR[c][m]);
                accI[c][m] = fma2(hv[c], sp, accI[c][m]);
            }
        }
    }
    #pragma unroll
    for (int c = 0; c < 5; c++)
        #pragma unroll
        for (int m = 0; m < 4; m++){
            float r0, r1, i0, i1;
            upk2(accR[c][m], r0, r1); upk2(accI[c][m], i0, i1);
            float r = r0 + r1, im = i0 + i1;
            #pragma unroll
            for (int off = 16; off >= 1; off >>= 1){
                r  += __shfl_down_sync(0xffffffffu, r,  off);
                im += __shfl_down_sync(0xffffffffu, im, off);
            }
            if (lane == 0){
                int base = (((chunk*B + b)*C + c0 + c)*M + (m0 + m));
                *(u64*)&g_partial[base*2] = pk2(r, im);   // Ts holds -sin
            }
        }
}

// lifting + forward DFT of h0
__global__ void __launch_bounds__(512, 1) k_lift_dft(const float* __restrict__ x,
                                                     const float* __restrict__ pd,
                                                     const float* __restrict__ fc0w,
                                                     const float* __restrict__ fc0b){
    const int b = blockIdx.y, chunk = blockIdx.x;
    const int s0 = chunk*PTS + threadIdx.x*2;
    const float inv = 1.0f / g_max[0];
    float2 xv = *(const float2*)&x[b*S + s0];
    float2 pv = *(const float2*)&pd[s0];
    u64 xp = pk2(xv.x, xv.y);
    u64 gp = pk2(pv.x*inv, pv.y*inv);
    #pragma unroll
    for (int c = 0; c < C; c++){
        u64 wa = pk2(fc0w[c], fc0w[c]);
        u64 wg = pk2(fc0w[C+c], fc0w[C+c]);
        u64 bb = pk2(fc0b[c], fc0b[c]);
        u64 o = fma2(xp, wa, fma2(gp, wg, bb));
        float o0, o1; upk2(o, o0, o1);
        *(float2*)&g_h0[((b*C + c) << 16) + s0] = make_float2(o0, o1);
    }
    __syncthreads();
    dft_phase(g_h0, b, chunk);
}

__global__ void k_reduceX(){
    int i = blockIdx.x*256 + threadIdx.x;
    if (i < B*C*M*2){
        float s = 0.f;
        #pragma unroll
        for (int k = 0; k < NCHUNK; k++) s += g_partial[k*(B*C*M*2) + i];
        g_X[i] = s;
    }
}

// complex channel mixing + irfft scaling (DC: Re only, x1/S; m>=1: x2/S)
__global__ void k_mix(const float* __restrict__ wre, const float* __restrict__ wim){
    int idx = blockIdx.x*256 + threadIdx.x;
    if (idx >= B*C*M) return;
    int b = idx / (C*M), r = idx % (C*M), co = r / M, m = r % M;
    float yr = 0.f, yi = 0.f;
    for (int ci = 0; ci < C; ci++){
        float xr = g_X[((b*C + ci)*M + m)*2];
        float xi = g_X[((b*C + ci)*M + m)*2 + 1];
        float wr = wre[(ci*C + co)*M + m];
        float wi = wim[(ci*C + co)*M + m];
        yr += xr*wr - xi*wi;
        yi += xr*wi + xi*wr;
    }
    const float invS = 1.0f / (float)S;
    if (m == 0){ yr *= invS; yi = 0.f; }
    else       { yr *= 2.0f*invS; yi *= 2.0f*invS; }
    g_Y[((b*C + co)*M + m)*2]     = yr;
    g_Y[((b*C + co)*M + m)*2 + 1] = yi;
}

// fused: inverse-DFT + 1x1 conv + bias + gelu + forward-DFT of output
__global__ void __launch_bounds__(512, 1) k_fused(const float* __restrict__ hin,
                                                  float* __restrict__ hout,
                                                  const float* __restrict__ ww,
                                                  const float* __restrict__ wb){
    __shared__ __align__(8) u64 Yr2[C][M];
    __shared__ __align__(8) u64 Yi2[C][M];
    __shared__ __align__(8) u64 W2[C][C];
    __shared__ float Y0b[C];
    const int b = blockIdx.y, chunk = blockIdx.x, tid = threadIdx.x;
    for (int idx = tid; idx < C*M; idx += 512){
        int co = idx >> 4, m = idx & 15;
        float yr = g_Y[((b*C + co)*M + m)*2];
        float yi = g_Y[((b*C + co)*M + m)*2 + 1];
        Yr2[co][m] = pk2(yr, yr);
        Yi2[co][m] = pk2(yi, yi);          // Ts = -sin handles the sign
        if (m == 0) Y0b[co] = yr + wb[co];
    }
    for (int idx = tid; idx < C*C; idx += 512){
        int o = idx / C, c = idx % C;
        float w = ww[o*C + c];
        W2[o][c] = pk2(w, w);
    }
    __syncthreads();
    const int s0 = chunk*PTS + tid*2;
    u64 a[C];
    #pragma unroll
    for (int co = 0; co < C; co++){ float v = Y0b[co]; a[co] = pk2(v, v); }
    #pragma unroll 4
    for (int ci = 0; ci < C; ci++){
        float2 hv = *(const float2*)&hin[((b*C + ci) << 16) + s0];
        u64 hp = pk2(hv.x, hv.y);
        #pragma unroll
        for (int co = 0; co < C; co++)
            a[co] = fma2(hp, W2[co][ci], a[co]);
    }
    #pragma unroll
    for (int m = 1; m < M; m++){
        float2 tc = *(const float2*)&g_Tc[(m<<16) + s0];
        float2 ts = *(const float2*)&g_Ts[(m<<16) + s0];
        u64 cp = pk2(tc.x, tc.y);
        u64 sp = pk2(ts.x, ts.y);
        #pragma unroll
        for (int co = 0; co < C; co++){
            a[co] = fma2(cp, Yr2[co][m], a[co]);
            a[co] = fma2(sp, Yi2[co][m], a[co]);
        }
    }
    #pragma unroll
    for (int co = 0; co < C; co++){
        float f0, f1; upk2(a[co], f0, f1);
        *(float2*)&hout[((b*C + co) << 16) + s0] = make_float2(geluf(f0), geluf(f1));
    }
    __syncthreads();
    dft_phase(hout, b, chunk);
}

// layer 3 (no gelu) fused with fc1+gelu+fc2 -> final output
__global__ void __launch_bounds__(128) k_final(const float* __restrict__ hin,
                                               const float* __restrict__ ww,
                                               const float* __restrict__ wb,
                                               const float* __restrict__ fc1w,
                                               const float* __restrict__ fc1b,
                                               const float* __restrict__ fc2w,
                                               const float* __restrict__ fc2b,
                                               float* __restrict__ out){
    __shared__ __align__(8) u64 Yr2[C][M];
    __shared__ __align__(8) u64 Yi2[C][M];
    __shared__ __align__(8) u64 W2[C][C];
    __shared__ float Y0b[C];
    __shared__ __align__(8) u64 F1[C][H];
    __shared__ float f1b[H];
    __shared__ float f2w[H];
    const int b = blockIdx.y, tid = threadIdx.x;
    for (int idx = tid; idx < C*M; idx += 128){
        int co = idx >> 4, m = idx & 15;
        float yr = g_Y[((b*C + co)*M + m)*2];
        float yi = g_Y[((b*C + co)*M + m)*2 + 1];
        Yr2[co][m] = pk2(yr, yr);
        Yi2[co][m] = pk2(yi, yi);
        if (m == 0) Y0b[co] = yr + wb[co];
    }
    for (int idx = tid; idx < C*C; idx += 128){
        int o = idx / C, c = idx % C;
        float w = ww[o*C + c];
        W2[o][c] = pk2(w, w);
    }
    for (int idx = tid; idx < C*H; idx += 128){
        int c = idx >> 7, j = idx & 127;
        float w = fc1w[c*H + j];
        F1[c][j] = pk2(w, w);
    }
    for (int idx = tid; idx < H; idx += 128){ f1b[idx] = fc1b[idx]; f2w[idx] = fc2w[idx]; }
    __syncthreads();
    const int s0 = (blockIdx.x*128 + tid)*4;
    u64 a0[C], a1[C];
    #pragma unroll
    for (int co = 0; co < C; co++){ float v = Y0b[co]; a0[co] = pk2(v, v); a1[co] = a0[co]; }
    for (int ci = 0; ci < C; ci++){
        float4 hv = *(const float4*)&hin[((b*C + ci) << 16) + s0];
        u64 hA = pk2(hv.x, hv.y), hB = pk2(hv.z, hv.w);
        #pragma unroll
        for (int co = 0; co < C; co++){
            u64 w = W2[co][ci];
            a0[co] = fma2(hA, w, a0[co]);
            a1[co] = fma2(hB, w, a1[co]);
        }
    }
    #pragma unroll
    for (int m = 1; m < M; m++){
        float4 tc = *(const float4*)&g_Tc[(m<<16) + s0];
        float4 ts = *(const float4*)&g_Ts[(m<<16) + s0];
        u64 cA = pk2(tc.x, tc.y), cB = pk2(tc.z, tc.w);
        u64 sA = pk2(ts.x, ts.y), sB = pk2(ts.z, ts.w);
        #pragma unroll
        for (int co = 0; co < C; co++){
            u64 yr = Yr2[co][m], yi = Yi2[co][m];
            a0[co] = fma2(cA, yr, a0[co]);
            a1[co] = fma2(cB, yr, a1[co]);
            a0[co] = fma2(sA, yi, a0[co]);
            a1[co] = fma2(sB, yi, a1[co]);
        }
    }
    float o0, o1, o2, o3;
    o0 = o1 = o2 = o3 = fc2b[0];
    for (int j = 0; j < H; j++){
        float bj = f1b[j];
        u64 t0 = pk2(bj, bj), t1 = t0;
        #pragma unroll
        for (int c = 0; c < C; c++){
            u64 f = F1[c][j];
            t0 = fma2(a0[c], f, t0);
            t1 = fma2(a1[c], f, t1);
        }
        float u0, u1, u2, u3;
        upk2(t0, u0, u1); upk2(t1, u2, u3);
        float w = f2w[j];
        o0 = fmaf(geluf(u0), w, o0);
        o1 = fmaf(geluf(u1), w, o1);
        o2 = fmaf(geluf(u2), w, o2);
        o3 = fmaf(geluf(u3), w, o3);
    }
    float4 res; res.x = o0; res.y = o1; res.z = o2; res.w = o3;
    *(float4*)&out[b*S + s0] = res;
}

extern "C" void kernel_launch(void* const* d_in, const int* in_sizes, int n_in,
                              void* d_out, int out_size){
    float *h0, *h1;
    cudaGetSymbolAddress((void**)&h0, g_h0);
    cudaGetSymbolAddress((void**)&h1, g_h1);

    const float* x    = (const float*)d_in[0];
    const float* pd   = (const float*)d_in[1];
    const float* fc0w = (const float*)d_in[2];
    const float* fc0b = (const float*)d_in[3];

    const float *swre[4], *swim[4], *wlw[4], *wlb[4];
    const float *fc1w, *fc1b, *fc2w, *fc2b;
    if (in_sizes[4] == C*C*M){           // signature order
        for (int l = 0; l < 4; l++){
            swre[l] = (const float*)d_in[4 + 4*l];
            swim[l] = (const float*)d_in[5 + 4*l];
            wlw[l]  = (const float*)d_in[6 + 4*l];
            wlb[l]  = (const float*)d_in[7 + 4*l];
        }
        fc1w = (const float*)d_in[20];
        fc1b = (const float*)d_in[21];
        fc2w = (const float*)d_in[22];
        fc2b = (const float*)d_in[23];
    } else {                             // dict-insertion order
        fc1w = (const float*)d_in[4];
        fc1b = (const float*)d_in[5];
        fc2w = (const float*)d_in[6];
        fc2b = (const float*)d_in[7];
        for (int l = 0; l < 4; l++){
            swre[l] = (const float*)d_in[8  + 4*l];
            swim[l] = (const float*)d_in[9  + 4*l];
            wlw[l]  = (const float*)d_in[10 + 4*l];
            wlb[l]  = (const float*)d_in[11 + 4*l];
        }
    }
    float* out = (float*)d_out;

    k_max<<<1, 1024>>>(pd);
    k_tables<<<64, 1024>>>();
    k_ttab<<<(M*S)/1024, 1024>>>();
    k_lift_dft<<<dim3(NCHUNK, B), 512>>>(x, pd, fc0w, fc0b);   // launch #4: profiled

    float* hin = h0;
    float* hout = h1;
    for (int l = 0; l < 4; l++){
        k_reduceX<<<(B*C*M*2 + 255)/256, 256>>>();
        k_mix<<<(B*C*M + 255)/256, 256>>>(swre[l], swim[l]);
        if (l < 3){
            k_fused<<<dim3(NCHUNK, B), 512>>>(hin, hout, wlw[l], wlb[l]);
            float* t = hin; hin = hout; hout = t;
        } else {
            k_final<<<dim3(S/512, B), 128>>>(hin, wlw[3], wlb[3],
                                             fc1w, fc1b, fc2w, fc2b, out);
        }
    }
}

// round 12
// speedup vs baseline: 1.5072x; 1.0587x over previous
#include <cuda_runtime.h>
#include <math.h>

#define S 65536
#define SMASK 65535
#define B 32
#define C 20
#define M 16
#define H 128
#define PTS 2048                 // points per fused block (512 thr x 4 pts)
#define NCHUNK (S/PTS)           // 32

typedef unsigned long long u64;

static __device__ float g_h0[B*C*S];
static __device__ float g_h1[B*C*S];
static __device__ float g_cs[S];
static __device__ float g_sn[S];
static __device__ float g_Tc[M*S];            // cos(2pi m s/S), m-major
static __device__ float g_Ts[M*S];            // -sin(2pi m s/S), m-major
static __device__ float g_partial[NCHUNK*B*C*M*2];
static __device__ float g_Y[B*C*M*2];
static __device__ float g_max[1];

__device__ __forceinline__ u64 pk2(float a, float b){
    u64 r; asm("mov.b64 %0,{%1,%2};" : "=l"(r) : "f"(a), "f"(b)); return r;
}
__device__ __forceinline__ void upk2(u64 v, float& a, float& b){
    asm("mov.b64 {%0,%1},%2;" : "=f"(a), "=f"(b) : "l"(v));
}
__device__ __forceinline__ u64 fma2(u64 a, u64 b, u64 c){
    u64 d; asm("fma.rn.f32x2 %0,%1,%2,%3;" : "=l"(d) : "l"(a), "l"(b), "l"(c)); return d;
}
// gelu via A&S 7.1.26 erf approx (|abs err| <= 1.5e-7), rcp.approx division
__device__ __forceinline__ float geluf(float x){
    float z  = 0.7071067811865476f * x;
    float az = fabsf(z);
    float d  = fmaf(0.3275911f, az, 1.0f);
    float t; asm("rcp.approx.f32 %0,%1;" : "=f"(t) : "f"(d));
    float p  = fmaf(1.061405429f, t, -1.453152027f);
    p = fmaf(p, t, 1.421413741f);
    p = fmaf(p, t, -0.284496736f);
    p = fmaf(p, t, 0.254829592f);
    p = p * t;
    float e  = __expf(-az*az);
    float er = fmaf(-p, e, 1.0f);          // erf(|z|)
    er = copysignf(er, z);
    return 0.5f * x * (1.0f + er);
}

__global__ void k_max(const float* __restrict__ pd){
    __shared__ float red[1024];
    int tid = threadIdx.x;
    float m = -1e30f;
    for (int i = tid; i < S; i += 1024) m = fmaxf(m, pd[i]);
    red[tid] = m; __syncthreads();
    for (int o = 512; o >= 1; o >>= 1){
        if (tid < o) red[tid] = fmaxf(red[tid], red[tid+o]);
        __syncthreads();
    }
    if (tid == 0) g_max[0] = red[0];
}

__global__ void k_tables(){
    int i = blockIdx.x*1024 + threadIdx.x;
    if (i < S){
        float ang = (float)i * 9.587379924285257e-5f;  // 2*pi/65536
        float s, c; sincosf(ang, &s, &c);
        g_cs[i] = c; g_sn[i] = s;
    }
}

__global__ void k_ttab(){
    int i = blockIdx.x*1024 + threadIdx.x;   // i = m*S + s
    int m = i >> 16, s = i & SMASK;
    int t = (m*s) & SMASK;
    g_Tc[i] = g_cs[t];
    g_Ts[i] = -g_sn[t];
}

// ---- block-local forward DFT over PTS points, float4 lanes ----
// 16 warps: warp tile = 5 channels x 4 modes; lane owns 4 samples per iter.
__device__ __forceinline__ void dft_phase(const float* __restrict__ hsrc,
                                          int b, int chunk){
    const int w = threadIdx.x >> 5, lane = threadIdx.x & 31;
    const int c0 = (w >> 2) * 5;      // 0,5,10,15
    const int m0 = (w & 3) * 4;       // 0,4,8,12
    const int p0 = chunk * PTS;
    u64 accR[5][4], accI[5][4];
    #pragma unroll
    for (int c = 0; c < 5; c++)
        #pragma unroll
        for (int m = 0; m < 4; m++){ accR[c][m] = 0ull; accI[c][m] = 0ull; }
    const float* hb = hsrc + ((b*C + c0) << 16);
    for (int it = 0; it < PTS/128; it++){
        const int s = p0 + it*128 + lane*4;
        u64 hA[5], hB[5];
        #pragma unroll
        for (int c = 0; c < 5; c++){
            float4 t = *(const float4*)&hb[(c<<16) + s];
            hA[c] = pk2(t.x, t.y); hB[c] = pk2(t.z, t.w);
        }
        #pragma unroll
        for (int m = 0; m < 4; m++){
            float4 tc = *(const float4*)&g_Tc[((m0+m)<<16) + s];
            float4 ts = *(const float4*)&g_Ts[((m0+m)<<16) + s];
            u64 cA = pk2(tc.x, tc.y), cB = pk2(tc.z, tc.w);
            u64 sA = pk2(ts.x, ts.y), sB = pk2(ts.z, ts.w);
            #pragma unroll
            for (int c = 0; c < 5; c++){
                accR[c][m] = fma2(hA[c], cA, accR[c][m]);
                accR[c][m] = fma2(hB[c], cB, accR[c][m]);
                accI[c][m] = fma2(hA[c], sA, accI[c][m]);
                accI[c][m] = fma2(hB[c], sB, accI[c][m]);
            }
        }
    }
    #pragma unroll
    for (int c = 0; c < 5; c++)
        #pragma unroll
        for (int m = 0; m < 4; m++){
            float r0, r1, i0, i1;
            upk2(accR[c][m], r0, r1); upk2(accI[c][m], i0, i1);
            float r = r0 + r1, im = i0 + i1;
            #pragma unroll
            for (int off = 16; off >= 1; off >>= 1){
                r  += __shfl_down_sync(0xffffffffu, r,  off);
                im += __shfl_down_sync(0xffffffffu, im, off);
            }
            if (lane == 0){
                int base = (((chunk*B + b)*C + c0 + c)*M + (m0 + m));
                *(u64*)&g_partial[base*2] = pk2(r, im);   // Ts holds -sin
            }
        }
}

// lifting (4-pt) + forward DFT of h0
__global__ void __launch_bounds__(512, 1) k_lift_dft(const float* __restrict__ x,
                                                     const float* __restrict__ pd,
                                                     const float* __restrict__ fc0w,
                                                     const float* __restrict__ fc0b){
    const int b = blockIdx.y, chunk = blockIdx.x;
    const int s0 = chunk*PTS + threadIdx.x*4;
    const float inv = 1.0f / g_max[0];
    float4 xv = *(const float4*)&x[b*S + s0];
    float4 pv = *(const float4*)&pd[s0];
    u64 xA = pk2(xv.x, xv.y), xB = pk2(xv.z, xv.w);
    u64 gA = pk2(pv.x*inv, pv.y*inv), gB = pk2(pv.z*inv, pv.w*inv);
    #pragma unroll
    for (int c = 0; c < C; c++){
        u64 wa = pk2(fc0w[c], fc0w[c]);
        u64 wg = pk2(fc0w[C+c], fc0w[C+c]);
        u64 bb = pk2(fc0b[c], fc0b[c]);
        u64 oA = fma2(xA, wa, fma2(gA, wg, bb));
        u64 oB = fma2(xB, wa, fma2(gB, wg, bb));
        float o0, o1, o2, o3; upk2(oA, o0, o1); upk2(oB, o2, o3);
        *(float4*)&g_h0[((b*C + c) << 16) + s0] = make_float4(o0, o1, o2, o3);
    }
    __syncthreads();
    dft_phase(g_h0, b, chunk);
}

// reduce partials + complex channel mixing + irfft scaling, one block per batch
__global__ void __launch_bounds__(512) k_mix(const float* __restrict__ wre,
                                             const float* __restrict__ wim){
    __shared__ float Xs[C*M*2];
    const int b = blockIdx.x, tid = threadIdx.x;
    for (int idx = tid; idx < C*M; idx += 512){
        float sr = 0.f, si = 0.f;
        #pragma unroll 4
        for (int k = 0; k < NCHUNK; k++){
            float2 p = *(const float2*)&g_partial[((k*B + b)*C*M + idx)*2];
            sr += p.x; si += p.y;
        }
        Xs[idx*2] = sr; Xs[idx*2+1] = si;
    }
    __syncthreads();
    for (int idx = tid; idx < C*M; idx += 512){
        int co = idx / M, m = idx % M;
        float yr = 0.f, yi = 0.f;
        #pragma unroll 4
        for (int ci = 0; ci < C; ci++){
            float xr = Xs[(ci*M + m)*2];
            float xi = Xs[(ci*M + m)*2 + 1];
            float wr = wre[(ci*C + co)*M + m];
            float wi = wim[(ci*C + co)*M + m];
            yr += xr*wr - xi*wi;
            yi += xr*wi + xi*wr;
        }
        const float invS = 1.0f / (float)S;
        if (m == 0){ yr *= invS; yi = 0.f; }
        else       { yr *= 2.0f*invS; yi *= 2.0f*invS; }
        g_Y[((b*C + co)*M + m)*2]     = yr;
        g_Y[((b*C + co)*M + m)*2 + 1] = yi;
    }
}

// fused: inverse-DFT + 1x1 conv + bias + gelu (4-pt, co-halved) + forward-DFT
__global__ void __launch_bounds__(512, 1) k_fused(const float* __restrict__ hin,
                                                  float* __restrict__ hout,
                                                  const float* __restrict__ ww,
                                                  const float* __restrict__ wb){
    __shared__ __align__(8) u64 Yr2[C][M];
    __shared__ __align__(8) u64 Yi2[C][M];
    __shared__ __align__(8) u64 W2[C][C];
    __shared__ float Y0b[C];
    const int b = blockIdx.y, chunk = blockIdx.x, tid = threadIdx.x;
    for (int idx = tid; idx < C*M; idx += 512){
        int co = idx >> 4, m = idx & 15;
        float yr = g_Y[((b*C + co)*M + m)*2];
        float yi = g_Y[((b*C + co)*M + m)*2 + 1];
        Yr2[co][m] = pk2(yr, yr);
        Yi2[co][m] = pk2(yi, yi);          // Ts = -sin handles the sign
        if (m == 0) Y0b[co] = yr + wb[co];
    }
    for (int idx = tid; idx < C*C; idx += 512){
        int o = idx / C, c = idx % C;
        float w = ww[o*C + c];
        W2[o][c] = pk2(w, w);
    }
    __syncthreads();
    const int s0 = chunk*PTS + tid*4;
    #pragma unroll
    for (int half = 0; half < 2; half++){
        const int cb = half*10;
        u64 aA[10], aB[10];
        #pragma unroll
        for (int co = 0; co < 10; co++){
            float v = Y0b[cb+co]; aA[co] = pk2(v, v); aB[co] = aA[co];
        }
        #pragma unroll 5
        for (int ci = 0; ci < C; ci++){
            float4 hv = *(const float4*)&hin[((b*C + ci) << 16) + s0];
            u64 hA = pk2(hv.x, hv.y), hB = pk2(hv.z, hv.w);
            #pragma unroll
            for (int co = 0; co < 10; co++){
                u64 w = W2[cb+co][ci];
                aA[co] = fma2(hA, w, aA[co]);
                aB[co] = fma2(hB, w, aB[co]);
            }
        }
        #pragma unroll 5
        for (int m = 1; m < M; m++){
            float4 tc = *(const float4*)&g_Tc[(m<<16) + s0];
            float4 ts = *(const float4*)&g_Ts[(m<<16) + s0];
            u64 cA = pk2(tc.x, tc.y), cB = pk2(tc.z, tc.w);
            u64 sA = pk2(ts.x, ts.y), sB = pk2(ts.z, ts.w);
            #pragma unroll
            for (int co = 0; co < 10; co++){
                u64 yr = Yr2[cb+co][m], yi = Yi2[cb+co][m];
                aA[co] = fma2(cA, yr, aA[co]);
                aB[co] = fma2(cB, yr, aB[co]);
                aA[co] = fma2(sA, yi, aA[co]);
                aB[co] = fma2(sB, yi, aB[co]);
            }
        }
        #pragma unroll
        for (int co = 0; co < 10; co++){
            float f0, f1, f2, f3;
            upk2(aA[co], f0, f1); upk2(aB[co], f2, f3);
            *(float4*)&hout[((b*C + cb + co) << 16) + s0] =
                make_float4(geluf(f0), geluf(f1), geluf(f2), geluf(f3));
        }
    }
    __syncthreads();
    dft_phase(hout, b, chunk);
}

// layer 3 (no gelu) fused with fc1+gelu+fc2 -> final output
__global__ void __launch_bounds__(128) k_final(const float* __restrict__ hin,
                                               const float* __restrict__ ww,
                                               const float* __restrict__ wb,
                                               const float* __restrict__ fc1w,
                                               const float* __restrict__ fc1b,
                                               const float* __restrict__ fc2w,
                                               const float* __restrict__ fc2b,
                                               float* __restrict__ out){
    __shared__ __align__(8) u64 Yr2[C][M];
    __shared__ __align__(8) u64 Yi2[C][M];
    __shared__ __align__(8) u64 W2[C][C];
    __shared__ float Y0b[C];
    __shared__ __align__(8) u64 F1[C][H];
    __shared__ float f1b[H];
    __shared__ float f2w[H];
    const int b = blockIdx.y, tid = threadIdx.x;
    for (int idx = tid; idx < C*M; idx += 128){
        int co = idx >> 4, m = idx & 15;
        float yr = g_Y[((b*C + co)*M + m)*2];
        float yi = g_Y[((b*C + co)*M + m)*2 + 1];
        Yr2[co][m] = pk2(yr, yr);
        Yi2[co][m] = pk2(yi, yi);
        if (m == 0) Y0b[co] = yr + wb[co];
    }
    for (int idx = tid; idx < C*C; idx += 128){
        int o = idx / C, c = idx % C;
        float w = ww[o*C + c];
        W2[o][c] = pk2(w, w);
    }
    for (int idx = tid; idx < C*H; idx += 128){
        int c = idx >> 7, j = idx & 127;
        float w = fc1w[c*H + j];
        F1[c][j] = pk2(w, w);
    }
    for (int idx = tid; idx < H; idx += 128){ f1b[idx] = fc1b[idx]; f2w[idx] = fc2w[idx]; }
    __syncthreads();
    const int s0 = (blockIdx.x*128 + tid)*4;
    u64 a0[C], a1[C];
    #pragma unroll
    for (int co = 0; co < C; co++){ float v = Y0b[co]; a0[co] = pk2(v, v); a1[co] = a0[co]; }
    for (int ci = 0; ci < C; ci++){
        float4 hv = *(const float4*)&hin[((b*C + ci) << 16) + s0];
        u64 hA = pk2(hv.x, hv.y), hB = pk2(hv.z, hv.w);
        #pragma unroll
        for (int co = 0; co < C; co++){
            u64 w = W2[co][ci];
            a0[co] = fma2(hA, w, a0[co]);
            a1[co] = fma2(hB, w, a1[co]);
        }
    }
    #pragma unroll
    for (int m = 1; m < M; m++){
        float4 tc = *(const float4*)&g_Tc[(m<<16) + s0];
        float4 ts = *(const float4*)&g_Ts[(m<<16) + s0];
        u64 cA = pk2(tc.x, tc.y), cB = pk2(tc.z, tc.w);
        u64 sA = pk2(ts.x, ts.y), sB = pk2(ts.z, ts.w);
        #pragma unroll
        for (int co = 0; co < C; co++){
            u64 yr = Yr2[co][m], yi = Yi2[co][m];
            a0[co] = fma2(cA, yr, a0[co]);
            a1[co] = fma2(cB, yr, a1[co]);
            a0[co] = fma2(sA, yi, a0[co]);
            a1[co] = fma2(sB, yi, a1[co]);
        }
    }
    float o0, o1, o2, o3;
    o0 = o1 = o2 = o3 = fc2b[0];
    for (int j = 0; j < H; j++){
        float bj = f1b[j];
        u64 t0 = pk2(bj, bj), t1 = t0;
        #pragma unroll
        for (int c = 0; c < C; c++){
            u64 f = F1[c][j];
            t0 = fma2(a0[c], f, t0);
            t1 = fma2(a1[c], f, t1);
        }
        float u0, u1, u2, u3;
        upk2(t0, u0, u1); upk2(t1, u2, u3);
        float w = f2w[j];
        o0 = fmaf(geluf(u0), w, o0);
        o1 = fmaf(geluf(u1), w, o1);
        o2 = fmaf(geluf(u2), w, o2);
        o3 = fmaf(geluf(u3), w, o3);
    }
    float4 res; res.x = o0; res.y = o1; res.z = o2; res.w = o3;
    *(float4*)&out[b*S + s0] = res;
}

extern "C" void kernel_launch(void* const* d_in, const int* in_sizes, int n_in,
                              void* d_out, int out_size){
    float *h0, *h1;
    cudaGetSymbolAddress((void**)&h0, g_h0);
    cudaGetSymbolAddress((void**)&h1, g_h1);

    const float* x    = (const float*)d_in[0];
    const float* pd   = (const float*)d_in[1];
    const float* fc0w = (const float*)d_in[2];
    const float* fc0b = (const float*)d_in[3];

    const float *swre[4], *swim[4], *wlw[4], *wlb[4];
    const float *fc1w, *fc1b, *fc2w, *fc2b;
    if (in_sizes[4] == C*C*M){           // signature order
        for (int l = 0; l < 4; l++){
            swre[l] = (const float*)d_in[4 + 4*l];
            swim[l] = (const float*)d_in[5 + 4*l];
            wlw[l]  = (const float*)d_in[6 + 4*l];
            wlb[l]  = (const float*)d_in[7 + 4*l];
        }
        fc1w = (const float*)d_in[20];
        fc1b = (const float*)d_in[21];
        fc2w = (const float*)d_in[22];
        fc2b = (const float*)d_in[23];
    } else {                             // dict-insertion order
        fc1w = (const float*)d_in[4];
        fc1b = (const float*)d_in[5];
        fc2w = (const float*)d_in[6];
        fc2b = (const float*)d_in[7];
        for (int l = 0; l < 4; l++){
            swre[l] = (const float*)d_in[8  + 4*l];
            swim[l] = (const float*)d_in[9  + 4*l];
            wlw[l]  = (const float*)d_in[10 + 4*l];
            wlb[l]  = (const float*)d_in[11 + 4*l];
        }
    }
    float* out = (float*)d_out;

    k_max<<<1, 1024>>>(pd);
    k_tables<<<64, 1024>>>();
    k_ttab<<<(M*S)/1024, 1024>>>();
    k_lift_dft<<<dim3(NCHUNK, B), 512>>>(x, pd, fc0w, fc0b);   // launch #4: profiled

    float* hin = h0;
    float* hout = h1;
    for (int l = 0; l < 4; l++){
        k_mix<<<B, 512>>>(swre[l], swim[l]);
        if (l < 3){
            k_fused<<<dim3(NCHUNK, B), 512>>>(hin, hout, wlw[l], wlb[l]);
            float* t = hin; hin = hout; hout = t;
        } else {
            k_final<<<dim3(S/512, B), 128>>>(hin, wlw[3], wlb[3],
                                             fc1w, fc1b, fc2w, fc2b, out);
        }
    }
}

// round 14
// speedup vs baseline: 1.5203x; 1.0087x over previous
#include <cuda_runtime.h>
#include <math.h>

#define S 65536
#define SMASK 65535
#define B 32
#define C 20
#define M 16
#define H 128
#define PTS 2048                 // points per fused block (512 thr x 4 pts)
#define NCHUNK (S/PTS)           // 32
#define HS_BYTES (C*PTS*4)       // 160 KB dynamic smem staging

typedef unsigned long long u64;

static __device__ float g_h0[B*C*S];
static __device__ float g_h1[B*C*S];
static __device__ float g_cs[S];
static __device__ float g_sn[S];
static __device__ float g_Tc[M*S];            // cos(2pi m s/S), m-major
static __device__ float g_Ts[M*S];            // -sin(2pi m s/S), m-major
static __device__ float g_partial[NCHUNK*B*C*M*2];
static __device__ float g_Y[B*C*M*2];
static __device__ float g_max[1];

__device__ __forceinline__ u64 pk2(float a, float b){
    u64 r; asm("mov.b64 %0,{%1,%2};" : "=l"(r) : "f"(a), "f"(b)); return r;
}
__device__ __forceinline__ void upk2(u64 v, float& a, float& b){
    asm("mov.b64 {%0,%1},%2;" : "=f"(a), "=f"(b) : "l"(v));
}
__device__ __forceinline__ u64 fma2(u64 a, u64 b, u64 c){
    u64 d; asm("fma.rn.f32x2 %0,%1,%2,%3;" : "=l"(d) : "l"(a), "l"(b), "l"(c)); return d;
}
// gelu via A&S 7.1.26 erf approx (|abs err| <= 1.5e-7), rcp.approx division
__device__ __forceinline__ float geluf(float x){
    float z  = 0.7071067811865476f * x;
    float az = fabsf(z);
    float d  = fmaf(0.3275911f, az, 1.0f);
    float t; asm("rcp.approx.f32 %0,%1;" : "=f"(t) : "f"(d));
    float p  = fmaf(1.061405429f, t, -1.453152027f);
    p = fmaf(p, t, 1.421413741f);
    p = fmaf(p, t, -0.284496736f);
    p = fmaf(p, t, 0.254829592f);
    p = p * t;
    float e  = __expf(-az*az);
    float er = fmaf(-p, e, 1.0f);          // erf(|z|)
    er = copysignf(er, z);
    return 0.5f * x * (1.0f + er);
}

__global__ void k_max(const float* __restrict__ pd){
    __shared__ float red[1024];
    int tid = threadIdx.x;
    float m = -1e30f;
    for (int i = tid; i < S; i += 1024) m = fmaxf(m, pd[i]);
    red[tid] = m; __syncthreads();
    for (int o = 512; o >= 1; o >>= 1){
        if (tid < o) red[tid] = fmaxf(red[tid], red[tid+o]);
        __syncthreads();
    }
    if (tid == 0) g_max[0] = red[0];
}

__global__ void k_tables(){
    int i = blockIdx.x*1024 + threadIdx.x;
    if (i < S){
        float ang = (float)i * 9.587379924285257e-5f;  // 2*pi/65536
        float s, c; sincosf(ang, &s, &c);
        g_cs[i] = c; g_sn[i] = s;
    }
}

__global__ void k_ttab(){
    int i = blockIdx.x*1024 + threadIdx.x;   // i = m*S + s
    int m = i >> 16, s = i & SMASK;
    int t = (m*s) & SMASK;
    g_Tc[i] = g_cs[t];
    g_Ts[i] = -g_sn[t];
}

// ---- block-local forward DFT over PTS points; h from SHARED memory ----
// 16 warps: warp tile = 5 channels x 4 modes; lane owns 4 samples per iter.
__device__ __forceinline__ void dft_phase_sm(const float* __restrict__ hs,
                                             int b, int chunk){
    const int w = threadIdx.x >> 5, lane = threadIdx.x & 31;
    const int c0 = (w >> 2) * 5;      // 0,5,10,15
    const int m0 = (w & 3) * 4;       // 0,4,8,12
    u64 accR[5][4], accI[5][4];
    #pragma unroll
    for (int c = 0; c < 5; c++)
        #pragma unroll
        for (int m = 0; m < 4; m++){ accR[c][m] = 0ull; accI[c][m] = 0ull; }
    for (int it = 0; it < PTS/128; it++){
        const int sl = it*128 + lane*4;            // local sample index
        const int sg = chunk*PTS + sl;             // global sample index
        u64 hA[5], hB[5];
        #pragma unroll
        for (int c = 0; c < 5; c++){
            float4 t = *(const float4*)&hs[(c0+c)*PTS + sl];
            hA[c] = pk2(t.x, t.y); hB[c] = pk2(t.z, t.w);
        }
        #pragma unroll
        for (int m = 0; m < 4; m++){
            float4 tc = *(const float4*)&g_Tc[((m0+m)<<16) + sg];
            float4 ts = *(const float4*)&g_Ts[((m0+m)<<16) + sg];
            u64 cA = pk2(tc.x, tc.y), cB = pk2(tc.z, tc.w);
            u64 sA = pk2(ts.x, ts.y), sB = pk2(ts.z, ts.w);
            #pragma unroll
            for (int c = 0; c < 5; c++){
                accR[c][m] = fma2(hA[c], cA, accR[c][m]);
                accR[c][m] = fma2(hB[c], cB, accR[c][m]);
                accI[c][m] = fma2(hA[c], sA, accI[c][m]);
                accI[c][m] = fma2(hB[c], sB, accI[c][m]);
            }
        }
    }
    #pragma unroll
    for (int c = 0; c < 5; c++)
        #pragma unroll
        for (int m = 0; m < 4; m++){
            float r0, r1, i0, i1;
            upk2(accR[c][m], r0, r1); upk2(accI[c][m], i0, i1);
            float r = r0 + r1, im = i0 + i1;
            #pragma unroll
            for (int off = 16; off >= 1; off >>= 1){
                r  += __shfl_down_sync(0xffffffffu, r,  off);
                im += __shfl_down_sync(0xffffffffu, im, off);
            }
            if (lane == 0){
                int base = (((chunk*B + b)*C + c0 + c)*M + (m0 + m));
                *(u64*)&g_partial[base*2] = pk2(r, im);   // Ts holds -sin
            }
        }
}

// lifting (4-pt) + forward DFT of h0 (staged through smem)
__global__ void __launch_bounds__(512, 1) k_lift_dft(const float* __restrict__ x,
                                                     const float* __restrict__ pd,
                                                     const float* __restrict__ fc0w,
                                                     const float* __restrict__ fc0b){
    extern __shared__ float h_sh[];
    const int b = blockIdx.y, chunk = blockIdx.x;
    const int sl = threadIdx.x*4;
    const int s0 = chunk*PTS + sl;
    const float inv = 1.0f / g_max[0];
    float4 xv = *(const float4*)&x[b*S + s0];
    float4 pv = *(const float4*)&pd[s0];
    u64 xA = pk2(xv.x, xv.y), xB = pk2(xv.z, xv.w);
    u64 gA = pk2(pv.x*inv, pv.y*inv), gB = pk2(pv.z*inv, pv.w*inv);
    #pragma unroll
    for (int c = 0; c < C; c++){
        u64 wa = pk2(fc0w[c], fc0w[c]);
        u64 wg = pk2(fc0w[C+c], fc0w[C+c]);
        u64 bb = pk2(fc0b[c], fc0b[c]);
        u64 oA = fma2(xA, wa, fma2(gA, wg, bb));
        u64 oB = fma2(xB, wa, fma2(gB, wg, bb));
        float o0, o1, o2, o3; upk2(oA, o0, o1); upk2(oB, o2, o3);
        float4 ov = make_float4(o0, o1, o2, o3);
        *(float4*)&g_h0[((b*C + c) << 16) + s0] = ov;
        *(float4*)&h_sh[c*PTS + sl] = ov;
    }
    __syncthreads();
    dft_phase_sm(h_sh, b, chunk);
}

// reduce partials + complex channel mixing + irfft scaling, one block per batch
__global__ void __launch_bounds__(512) k_mix(const float* __restrict__ wre,
                                             const float* __restrict__ wim){
    __shared__ float Xs[C*M*2];
    const int b = blockIdx.x, tid = threadIdx.x;
    for (int idx = tid; idx < C*M; idx += 512){
        float sr = 0.f, si = 0.f;
        #pragma unroll 4
        for (int k = 0; k < NCHUNK; k++){
            float2 p = *(const float2*)&g_partial[((k*B + b)*C*M + idx)*2];
            sr += p.x; si += p.y;
        }
        Xs[idx*2] = sr; Xs[idx*2+1] = si;
    }
    __syncthreads();
    for (int idx = tid; idx < C*M; idx += 512){
        int co = idx / M, m = idx % M;
        float yr = 0.f, yi = 0.f;
        #pragma unroll 4
        for (int ci = 0; ci < C; ci++){
            float xr = Xs[(ci*M + m)*2];
            float xi = Xs[(ci*M + m)*2 + 1];
            float wr = wre[(ci*C + co)*M + m];
            float wi = wim[(ci*C + co)*M + m];
            yr += xr*wr - xi*wi;
            yi += xr*wi + xi*wr;
        }
        const float invS = 1.0f / (float)S;
        if (m == 0){ yr *= invS; yi = 0.f; }
        else       { yr *= 2.0f*invS; yi *= 2.0f*invS; }
        g_Y[((b*C + co)*M + m)*2]     = yr;
        g_Y[((b*C + co)*M + m)*2 + 1] = yi;
    }
}

// fused: inverse-DFT + 1x1 conv + bias + gelu (4-pt, co-halved) + forward-DFT
__global__ void __launch_bounds__(512, 1) k_fused(const float* __restrict__ hin,
                                                  float* __restrict__ hout,
                                                  const float* __restrict__ ww,
                                                  const float* __restrict__ wb){
    extern __shared__ float h_sh[];
    __shared__ __align__(8) u64 Yr2[C][M];
    __shared__ __align__(8) u64 Yi2[C][M];
    __shared__ __align__(8) u64 W2[C][C];
    __shared__ float Y0b[C];
    const int b = blockIdx.y, chunk = blockIdx.x, tid = threadIdx.x;
    for (int idx = tid; idx < C*M; idx += 512){
        int co = idx >> 4, m = idx & 15;
        float yr = g_Y[((b*C + co)*M + m)*2];
        float yi = g_Y[((b*C + co)*M + m)*2 + 1];
        Yr2[co][m] = pk2(yr, yr);
        Yi2[co][m] = pk2(yi, yi);          // Ts = -sin handles the sign
        if (m == 0) Y0b[co] = yr + wb[co];
    }
    for (int idx = tid; idx < C*C; idx += 512){
        int o = idx / C, c = idx % C;
        float w = ww[o*C + c];
        W2[o][c] = pk2(w, w);
    }
    __syncthreads();
    const int sl = tid*4;
    const int s0 = chunk*PTS + sl;
    #pragma unroll
    for (int half = 0; half < 2; half++){
        const int cb = half*10;
        u64 aA[10], aB[10];
        #pragma unroll
        for (int co = 0; co < 10; co++){
            float v = Y0b[cb+co]; aA[co] = pk2(v, v); aB[co] = aA[co];
        }
        #pragma unroll 5
        for (int ci = 0; ci < C; ci++){
            float4 hv = *(const float4*)&hin[((b*C + ci) << 16) + s0];
            u64 hA = pk2(hv.x, hv.y), hB = pk2(hv.z, hv.w);
            #pragma unroll
            for (int co = 0; co < 10; co++){
                u64 w = W2[cb+co][ci];
                aA[co] = fma2(hA, w, aA[co]);
                aB[co] = fma2(hB, w, aB[co]);
            }
        }
        #pragma unroll 5
        for (int m = 1; m < M; m++){
            float4 tc = *(const float4*)&g_Tc[(m<<16) + s0];
            float4 ts = *(const float4*)&g_Ts[(m<<16) + s0];
            u64 cA = pk2(tc.x, tc.y), cB = pk2(tc.z, tc.w);
            u64 sA = pk2(ts.x, ts.y), sB = pk2(ts.z, ts.w);
            #pragma unroll
            for (int co = 0; co < 10; co++){
                u64 yr = Yr2[cb+co][m], yi = Yi2[cb+co][m];
                aA[co] = fma2(cA, yr, aA[co]);
                aB[co] = fma2(cB, yr, aB[co]);
                aA[co] = fma2(sA, yi, aA[co]);
                aB[co] = fma2(sB, yi, aB[co]);
            }
        }
        #pragma unroll
        for (int co = 0; co < 10; co++){
            float f0, f1, f2, f3;
            upk2(aA[co], f0, f1); upk2(aB[co], f2, f3);
            float4 ov = make_float4(geluf(f0), geluf(f1), geluf(f2), geluf(f3));
            *(float4*)&hout[((b*C + cb + co) << 16) + s0] = ov;
            *(float4*)&h_sh[(cb + co)*PTS + sl] = ov;
        }
    }
    __syncthreads();
    dft_phase_sm(h_sh, b, chunk);
}

// layer 3 (no gelu) fused with fc1+gelu+fc2 -> final output
__global__ void __launch_bounds__(128) k_final(const float* __restrict__ hin,
                                               const float* __restrict__ ww,
                                               const float* __restrict__ wb,
                                               const float* __restrict__ fc1w,
                                               const float* __restrict__ fc1b,
                                               const float* __restrict__ fc2w,
                                               const float* __restrict__ fc2b,
                                               float* __restrict__ out){
    __shared__ __align__(8) u64 Yr2[C][M];
    __shared__ __align__(8) u64 Yi2[C][M];
    __shared__ __align__(8) u64 W2[C][C];
    __shared__ float Y0b[C];
    __shared__ __align__(8) u64 F1[C][H];
    __shared__ float f1b[H];
    __shared__ float f2w[H];
    const int b = blockIdx.y, tid = threadIdx.x;
    for (int idx = tid; idx < C*M; idx += 128){
        int co = idx >> 4, m = idx & 15;
        float yr = g_Y[((b*C + co)*M + m)*2];
        float yi = g_Y[((b*C + co)*M + m)*2 + 1];
        Yr2[co][m] = pk2(yr, yr);
        Yi2[co][m] = pk2(yi, yi);
        if (m == 0) Y0b[co] = yr + wb[co];
    }
    for (int idx = tid; idx < C*C; idx += 128){
        int o = idx / C, c = idx % C;
        float w = ww[o*C + c];
        W2[o][c] = pk2(w, w);
    }
    for (int idx = tid; idx < C*H; idx += 128){
        int c = idx >> 7, j = idx & 127;
        float w = fc1w[c*H + j];
        F1[c][j] = pk2(w, w);
    }
    for (int idx = tid; idx < H; idx += 128){ f1b[idx] = fc1b[idx]; f2w[idx] = fc2w[idx]; }
    __syncthreads();
    const int s0 = (blockIdx.x*128 + tid)*4;
    u64 a0[C], a1[C];
    #pragma unroll
    for (int co = 0; co < C; co++){ float v = Y0b[co]; a0[co] = pk2(v, v); a1[co] = a0[co]; }
    for (int ci = 0; ci < C; ci++){
        float4 hv = *(const float4*)&hin[((b*C + ci) << 16) + s0];
        u64 hA = pk2(hv.x, hv.y), hB = pk2(hv.z, hv.w);
        #pragma unroll
        for (int co = 0; co < C; co++){
            u64 w = W2[co][ci];
            a0[co] = fma2(hA, w, a0[co]);
            a1[co] = fma2(hB, w, a1[co]);
        }
    }
    #pragma unroll
    for (int m = 1; m < M; m++){
        float4 tc = *(const float4*)&g_Tc[(m<<16) + s0];
        float4 ts = *(const float4*)&g_Ts[(m<<16) + s0];
        u64 cA = pk2(tc.x, tc.y), cB = pk2(tc.z, tc.w);
        u64 sA = pk2(ts.x, ts.y), sB = pk2(ts.z, ts.w);
        #pragma unroll
        for (int co = 0; co < C; co++){
            u64 yr = Yr2[co][m], yi = Yi2[co][m];
            a0[co] = fma2(cA, yr, a0[co]);
            a1[co] = fma2(cB, yr, a1[co]);
            a0[co] = fma2(sA, yi, a0[co]);
            a1[co] = fma2(sB, yi, a1[co]);
        }
    }
    float o0, o1, o2, o3;
    o0 = o1 = o2 = o3 = fc2b[0];
    for (int j = 0; j < H; j++){
        float bj = f1b[j];
        u64 t0 = pk2(bj, bj), t1 = t0;
        #pragma unroll
        for (int c = 0; c < C; c++){
            u64 f = F1[c][j];
            t0 = fma2(a0[c], f, t0);
            t1 = fma2(a1[c], f, t1);
        }
        float u0, u1, u2, u3;
        upk2(t0, u0, u1); upk2(t1, u2, u3);
        float w = f2w[j];
        o0 = fmaf(geluf(u0), w, o0);
        o1 = fmaf(geluf(u1), w, o1);
        o2 = fmaf(geluf(u2), w, o2);
        o3 = fmaf(geluf(u3), w, o3);
    }
    float4 res; res.x = o0; res.y = o1; res.z = o2; res.w = o3;
    *(float4*)&out[b*S + s0] = res;
}

extern "C" void kernel_launch(void* const* d_in, const int* in_sizes, int n_in,
                              void* d_out, int out_size){
    float *h0, *h1;
    cudaGetSymbolAddress((void**)&h0, g_h0);
    cudaGetSymbolAddress((void**)&h1, g_h1);
    cudaFuncSetAttribute(k_lift_dft, cudaFuncAttributeMaxDynamicSharedMemorySize, HS_BYTES);
    cudaFuncSetAttribute(k_fused,    cudaFuncAttributeMaxDynamicSharedMemorySize, HS_BYTES);

    const float* x    = (const float*)d_in[0];
    const float* pd   = (const float*)d_in[1];
    const float* fc0w = (const float*)d_in[2];
    const float* fc0b = (const float*)d_in[3];

    const float *swre[4], *swim[4], *wlw[4], *wlb[4];
    const float *fc1w, *fc1b, *fc2w, *fc2b;
    if (in_sizes[4] == C*C*M){           // signature order
        for (int l = 0; l < 4; l++){
            swre[l] = (const float*)d_in[4 + 4*l];
            swim[l] = (const float*)d_in[5 + 4*l];
            wlw[l]  = (const float*)d_in[6 + 4*l];
            wlb[l]  = (const float*)d_in[7 + 4*l];
        }
        fc1w = (const float*)d_in[20];
        fc1b = (const float*)d_in[21];
        fc2w = (const float*)d_in[22];
        fc2b = (const float*)d_in[23];
    } else {                             // dict-insertion order
        fc1w = (const float*)d_in[4];
        fc1b = (const float*)d_in[5];
        fc2w = (const float*)d_in[6];
        fc2b = (const float*)d_in[7];
        for (int l = 0; l < 4; l++){
            swre[l] = (const float*)d_in[8  + 4*l];
            swim[l] = (const float*)d_in[9  + 4*l];
            wlw[l]  = (const float*)d_in[10 + 4*l];
            wlb[l]  = (const float*)d_in[11 + 4*l];
        }
    }
    float* out = (float*)d_out;

    k_max<<<1, 1024>>>(pd);
    k_tables<<<64, 1024>>>();
    k_ttab<<<(M*S)/1024, 1024>>>();
    k_lift_dft<<<dim3(NCHUNK, B), 512, HS_BYTES>>>(x, pd, fc0w, fc0b);  // launch #4: profiled

    float* hin = h0;
    float* hout = h1;
    for (int l = 0; l < 4; l++){
        k_mix<<<B, 512>>>(swre[l], swim[l]);
        if (l < 3){
            k_fused<<<dim3(NCHUNK, B), 512, HS_BYTES>>>(hin, hout, wlw[l], wlb[l]);
            float* t = hin; hin = hout; hout = t;
        } else {
            k_final<<<dim3(S/512, B), 128>>>(hin, wlw[3], wlb[3],
                                             fc1w, fc1b, fc2w, fc2b, out);
        }
    }
}